// round 13
// baseline (speedup 1.0000x reference)
#include <cuda_runtime.h>
#include <cuda_fp16.h>
#include <math.h>
#include <stdint.h>

// Problem constants
#define SEQ     2048
#define NEMBD   2560
#define NHEAD   32
#define HDIM    80
#define RD      32
#define OPSIZE  7680   // 3 * NEMBD

// ---------------------------------------------------------------------------
// Static device scratch (allocation-free per harness rules)
// ---------------------------------------------------------------------------
__device__ float g_qkv[SEQ * OPSIZE];
__device__ __half g_Ha[SEQ * NEMBD];           // hidden, fp16 trunc
__device__ __half g_Ca[SEQ * NEMBD];           // attention out, fp16
__device__ __half g_Qh[NHEAD * SEQ * HDIM];    // head-major Q (scaled)
__device__ __half g_Kh[NHEAD * SEQ * HDIM];
__device__ __half g_Vh[NHEAD * SEQ * HDIM];

// ---------------------------------------------------------------------------
// Helpers (base-target instructions only: cp.async / ldmatrix / mma.sync)
// ---------------------------------------------------------------------------
__device__ __forceinline__ uint32_t smem_u32(const void* p) {
    uint32_t a;
    asm("{ .reg .u64 t; cvta.to.shared.u64 t, %1; cvt.u32.u64 %0, t; }"
        : "=r"(a) : "l"(p));
    return a;
}
#define SWZ128(o) ((o) ^ (((o) >> 3) & 0x70))
// Padded-atom tile offset: rows of 128 fp16 logical cols, atoms 8r x 64c
#define TOFF(r, c) ((((r) >> 3) * 2048) + ((((c) >> 6)) << 10) + \
                    SWZ128((((r) & 7) << 7) + (((c) & 63) << 1)))

__device__ __forceinline__ void cp_async16(uint32_t s, const void* g) {
    asm volatile("cp.async.cg.shared.global [%0], [%1], 16;\n" :: "r"(s), "l"(g));
}

__device__ __forceinline__ void ldsm4(uint32_t* r, uint32_t a) {
    asm volatile("ldmatrix.sync.aligned.m8n8.x4.shared.b16 {%0,%1,%2,%3}, [%4];"
        : "=r"(r[0]), "=r"(r[1]), "=r"(r[2]), "=r"(r[3]) : "r"(a));
}
__device__ __forceinline__ void ldsm4t(uint32_t* r, uint32_t a) {
    asm volatile("ldmatrix.sync.aligned.m8n8.x4.trans.shared.b16 {%0,%1,%2,%3}, [%4];"
        : "=r"(r[0]), "=r"(r[1]), "=r"(r[2]), "=r"(r[3]) : "r"(a));
}

__device__ __forceinline__ void mma16816h(float* d, const uint32_t* a, const uint32_t* b) {
    asm volatile(
        "mma.sync.aligned.m16n8k16.row.col.f32.f16.f16.f32 "
        "{%0,%1,%2,%3}, {%4,%5,%6,%7}, {%8,%9}, {%0,%1,%2,%3};"
        : "+f"(d[0]), "+f"(d[1]), "+f"(d[2]), "+f"(d[3])
        : "r"(a[0]), "r"(a[1]), "r"(a[2]), "r"(a[3]), "r"(b[0]), "r"(b[1]));
}

__device__ __forceinline__ uint32_t h2u(float a, float b) {
    __half2 h = __floats2half2_rn(a, b);
    return *(uint32_t*)&h;
}

// ---------------------------------------------------------------------------
// fp32 -> fp16 truncate (activations)
// ---------------------------------------------------------------------------
__global__ void cvt_trunc(const float* __restrict__ x,
                          __half* __restrict__ h, int n4) {
    int i = blockIdx.x * blockDim.x + threadIdx.x;
    if (i >= n4) return;
    float4 v = ((const float4*)x)[i];
    __half2* hp = (__half2*)(h + i * 4);
    hp[0] = __floats2half2_rn(v.x, v.y);
    hp[1] = __floats2half2_rn(v.z, v.w);
}

// ---------------------------------------------------------------------------
// Fused HMMA GEMM with in-kernel fp32 weight hi/lo split:
//   C[m,n] = sum_k A[m,k] * B32[n,k] + bias[n]
// A: fp16 (pre-truncated activations), B32: raw fp32 weights.
// Per K-chunk (64): B32 staged to smem scratch via cp.async, each thread
// converts the chunks it loaded into SW128-swizzled Bh/Bl fp16 tiles
// (RN hi + RN residual), then 2-product MMA: C = A*Bh + A*Bl = A*B.
// fp16 stages mod-3, fp32 scratch mod-2; convert(c+1) overlaps MMA(c).
// MT = m-tiles per warp: block is (2*MT*16) x 128. 8 warps (2x4).
// ---------------------------------------------------------------------------
template<int MT>
__global__ __launch_bounds__(256, 1)
void gemm_fused(const __half* __restrict__ Ah, const float* __restrict__ B32,
                const float* __restrict__ bias, float* __restrict__ C,
                int M, int N, int K) {
    extern __shared__ char sm[];
    const uint32_t smb = smem_u32(sm);
    constexpr int ATILE = MT * 32 * 128;        // A fp16 stage bytes
    constexpr int OBH = ATILE;
    constexpr int OBL = ATILE + 16384;
    constexpr int SBF = ATILE + 32768;          // fp16 stage stride
    constexpr int SCB = 3 * SBF;                // fp32 scratch base

    const int tid  = threadIdx.x;
    const int lane = tid & 31;
    const int wid  = tid >> 5;
    const int wm   = wid >> 2;                  // 0..1
    const int wn   = wid & 3;                   // 0..3
    const int m0 = blockIdx.y * (MT * 32);
    const int n0 = blockIdx.x * 128;
    const int NC = K / 64;

    const __half* Ag = Ah + (size_t)m0 * K;
    const float*  Bg = B32 + (size_t)n0 * K;

    float acc[MT][4][4];
    #pragma unroll
    for (int mt = 0; mt < MT; mt++)
        #pragma unroll
        for (int nt = 0; nt < 4; nt++)
            #pragma unroll
            for (int q = 0; q < 4; q++) acc[mt][nt][q] = 0.f;

    // Issue loads for chunk c: A fp16 -> stage(c%3), B fp32 -> scratch(c&1)
    auto load_stage = [&](int c) {
        const uint32_t stA = smb + (c % 3) * SBF;
        const uint32_t sc  = smb + SCB + (c & 1) * 32768;
        const int k0 = c * 64;
        #pragma unroll
        for (int i = 0; i < MT; i++) {
            int id = tid + i * 256;
            int r = id >> 3, cc = id & 7;
            cp_async16(stA + SWZ128((uint32_t)(r * 128 + cc * 16)),
                       Ag + (size_t)r * K + k0 + cc * 8);
        }
        #pragma unroll
        for (int i = 0; i < 8; i++) {
            int id = tid + i * 256;
            int r = id >> 4, kc = id & 15;
            cp_async16(sc + id * 16, Bg + (size_t)r * K + k0 + kc * 4);
        }
        asm volatile("cp.async.commit_group;" ::: "memory");
    };

    // Convert chunk c's fp32 scratch -> Bh/Bl fp16 tiles (same chunks this
    // thread cp.async'd, so wait_group gives visibility without a barrier).
    auto convert = [&](int c) {
        char* src = sm + SCB + (c & 1) * 32768;
        char* dh  = sm + (c % 3) * SBF + OBH;
        char* dl  = sm + (c % 3) * SBF + OBL;
        #pragma unroll
        for (int i = 0; i < 8; i++) {
            int id = tid + i * 256;
            float4 v = *(const float4*)(src + id * 16);
            __half2 h0 = __floats2half2_rn(v.x, v.y);
            __half2 h1 = __floats2half2_rn(v.z, v.w);
            float2 f0 = __half22float2(h0), f1 = __half22float2(h1);
            __half2 l0 = __floats2half2_rn(v.x - f0.x, v.y - f0.y);
            __half2 l1 = __floats2half2_rn(v.z - f1.x, v.w - f1.y);
            int r = id >> 4, kc = id & 15;
            uint32_t off = SWZ128((uint32_t)(r * 128 + (kc >> 1) * 16)) + (kc & 1) * 8;
            uint2 ph, pl;
            ph.x = *(uint32_t*)&h0; ph.y = *(uint32_t*)&h1;
            pl.x = *(uint32_t*)&l0; pl.y = *(uint32_t*)&l1;
            *(uint2*)(dh + off) = ph;
            *(uint2*)(dl + off) = pl;
        }
    };

    // Prologue: chunks 0 and 1 in flight; convert 0.
    load_stage(0);
    load_stage(1);
    asm volatile("cp.async.wait_group 1;" ::: "memory");
    convert(0);
    __syncthreads();

    const int arow = wm * (MT * 16) + (lane & 7) + ((lane >> 3) & 1) * 8;
    const int akb  = (lane >> 4) * 16;
    const int brow = wn * 32 + (lane >> 4) * 8 + (lane & 7);
    const int bkb  = ((lane >> 3) & 1) * 16;

    for (int c = 0; c < NC; c++) {
        if (c + 2 < NC) load_stage(c + 2);
        if (c + 1 < NC) {
            if (c + 2 < NC) asm volatile("cp.async.wait_group 1;" ::: "memory");
            else            asm volatile("cp.async.wait_group 0;" ::: "memory");
            convert(c + 1);
        }

        const uint32_t stg = smb + (c % 3) * SBF;
        #pragma unroll
        for (int ks = 0; ks < 4; ks++) {
            uint32_t ah[MT][4], bh[4][2], bl[4][2];
            #pragma unroll
            for (int mt = 0; mt < MT; mt++) {
                uint32_t so = SWZ128((uint32_t)((arow + mt * 16) * 128 + ks * 32 + akb));
                ldsm4(ah[mt], stg + so);
            }
            #pragma unroll
            for (int jj = 0; jj < 2; jj++) {
                uint32_t so = SWZ128((uint32_t)((brow + jj * 16) * 128 + ks * 32 + bkb));
                uint32_t t[4];
                ldsm4(t, stg + OBH + so);
                bh[jj * 2][0] = t[0]; bh[jj * 2][1] = t[1];
                bh[jj * 2 + 1][0] = t[2]; bh[jj * 2 + 1][1] = t[3];
                ldsm4(t, stg + OBL + so);
                bl[jj * 2][0] = t[0]; bl[jj * 2][1] = t[1];
                bl[jj * 2 + 1][0] = t[2]; bl[jj * 2 + 1][1] = t[3];
            }
            #pragma unroll
            for (int mt = 0; mt < MT; mt++)
                #pragma unroll
                for (int nt = 0; nt < 4; nt++)
                    mma16816h(acc[mt][nt], ah[mt], bh[nt]);
            #pragma unroll
            for (int mt = 0; mt < MT; mt++)
                #pragma unroll
                for (int nt = 0; nt < 4; nt++)
                    mma16816h(acc[mt][nt], ah[mt], bl[nt]);
        }
        __syncthreads();
    }

    // Epilogue: bias add + store
    const int rb = m0 + wm * (MT * 16) + (lane >> 2);
    const int cb = n0 + wn * 32 + (lane & 3) * 2;
    #pragma unroll
    for (int mt = 0; mt < MT; mt++) {
        #pragma unroll
        for (int nt = 0; nt < 4; nt++) {
            int r0 = rb + mt * 16;
            int cc = cb + nt * 8;
            float2 b = *(const float2*)(bias + cc);
            float2 v0, v1;
            v0.x = acc[mt][nt][0] + b.x; v0.y = acc[mt][nt][1] + b.y;
            v1.x = acc[mt][nt][2] + b.x; v1.y = acc[mt][nt][3] + b.y;
            *(float2*)(C + (size_t)r0 * N + cc)       = v0;
            *(float2*)(C + (size_t)(r0 + 8) * N + cc) = v1;
        }
    }
}

#define GEMM_SMEM_MT4 (3 * (16384 + 32768) + 65536)   // 212992
#define GEMM_SMEM_MT2 (3 * (8192 + 32768) + 65536)    // 188416

// ---------------------------------------------------------------------------
// Fused RoPE (no sign flip) + fp16 pack to head-major [NHEAD][SEQ][80].
// Q pre-scaled by 1/sqrt(80).
// ---------------------------------------------------------------------------
__global__ void rope_pack(const float* __restrict__ qkv,
                          const float* __restrict__ cosT,
                          const float* __restrict__ sinT,
                          __half* __restrict__ Qh, __half* __restrict__ Kh,
                          __half* __restrict__ Vh) {
    int idx = blockIdx.x * blockDim.x + threadIdx.x;
    if (idx >= SEQ * NHEAD * HDIM) return;
    int d  = idx % HDIM;
    int th = idx / HDIM;
    int h  = th & 31;
    int t  = th >> 5;

    const float* base = qkv + (size_t)t * OPSIZE + h * HDIM;
    float q = base[d];
    float k = base[NEMBD + d];
    float v = base[2 * NEMBD + d];
    if (d < RD) {
        float c = cosT[t * RD + d];
        float s = sinT[t * RD + d];
        int dp = (d < 16) ? d + 16 : d - 16;
        q = q * c + base[dp] * s;
        k = k * c + base[NEMBD + dp] * s;
    }
    size_t o = ((size_t)h * SEQ + t) * HDIM + d;
    Qh[o] = __float2half(q * 0.11180339887498948f);
    Kh[o] = __float2half(k);
    Vh[o] = __float2half(v);
}

// ---------------------------------------------------------------------------
// HMMA fp16 flash attention (causal). Grid (qb, head), 128 threads (4 warps).
// BQ = BK = 64. Warp owns 16 q-rows. Smem: Q 16K + 2 stages x (K 16K + V 16K).
// Writes O directly as fp16 into att[t][h*80+d] (GEMM2 A operand).
// ---------------------------------------------------------------------------
#define FA_SMEM (16384 + 2 * 32768)   // 81920

__global__ __launch_bounds__(128, 2)
void flash_fp16(const __half* __restrict__ Qh, const __half* __restrict__ Kh,
                const __half* __restrict__ Vh, __half* __restrict__ att) {
    extern __shared__ char sm[];
    const uint32_t smb = smem_u32(sm);
    const int h = blockIdx.y;
    const int qb = blockIdx.x;
    const int q0 = qb * 64;
    const int tid = threadIdx.x;
    const int lane = tid & 31;
    const int wid = tid >> 5;

    const __half* Qg = Qh + ((size_t)h * SEQ + q0) * HDIM;
    const __half* Kg = Kh + (size_t)h * SEQ * HDIM;
    const __half* Vg = Vh + (size_t)h * SEQ * HDIM;

    const uint32_t SQ = smb;

    #pragma unroll
    for (int i = 0; i < 5; i++) {
        int id = tid + i * 128;
        int r = id / 10, c = id - r * 10;
        cp_async16(SQ + TOFF(r, c * 8), Qg + r * HDIM + c * 8);
    }
    asm volatile("cp.async.commit_group;" ::: "memory");

    auto load_kv = [&](int kb, int s) {
        const __half* kg = Kg + (size_t)kb * 64 * HDIM;
        const __half* vg = Vg + (size_t)kb * 64 * HDIM;
        uint32_t SK = smb + 16384 + s * 32768;
        uint32_t SV = SK + 16384;
        #pragma unroll
        for (int i = 0; i < 5; i++) {
            int id = tid + i * 128;
            int r = id / 10, c = id - r * 10;
            uint32_t o = TOFF(r, c * 8);
            cp_async16(SK + o, kg + r * HDIM + c * 8);
            cp_async16(SV + o, vg + r * HDIM + c * 8);
        }
        asm volatile("cp.async.commit_group;" ::: "memory");
    };

    load_kv(0, 0);
    asm volatile("cp.async.wait_group 0;" ::: "memory");
    __syncthreads();

    uint32_t qf[5][4];
    {
        int row = wid * 16 + (lane & 7) + ((lane >> 3) & 1) * 8;
        #pragma unroll
        for (int ks = 0; ks < 5; ks++) {
            int col = ks * 16 + (lane >> 4) * 8;
            ldsm4(qf[ks], SQ + TOFF(row, col));
        }
    }

    float m0 = -1e30f, m1 = -1e30f, l0 = 0.f, l1 = 0.f;
    float oa[10][4];
    #pragma unroll
    for (int dt = 0; dt < 10; dt++)
        #pragma unroll
        for (int q = 0; q < 4; q++) oa[dt][q] = 0.f;

    const int krow = (lane >> 4) * 8 + (lane & 7);
    const int kcol = ((lane >> 3) & 1) * 8;
    const int vrow = (lane & 7) + ((lane >> 3) & 1) * 8;
    const int vcol = (lane >> 4) * 8;

    for (int kb = 0; kb <= qb; kb++) {
        const int s = kb & 1;
        if (kb < qb) {
            load_kv(kb + 1, s ^ 1);
            asm volatile("cp.async.wait_group 1;" ::: "memory");
        } else {
            asm volatile("cp.async.wait_group 0;" ::: "memory");
        }
        __syncthreads();
        const uint32_t SK = smb + 16384 + s * 32768;
        const uint32_t SV = SK + 16384;

        float sa[8][4];
        #pragma unroll
        for (int nt = 0; nt < 8; nt++)
            #pragma unroll
            for (int q = 0; q < 4; q++) sa[nt][q] = 0.f;

        #pragma unroll
        for (int ks = 0; ks < 5; ks++) {
            int col = ks * 16 + kcol;
            #pragma unroll
            for (int np = 0; np < 4; np++) {
                uint32_t t[4];
                ldsm4(t, SK + TOFF(np * 16 + krow, col));
                uint32_t b0[2] = { t[0], t[1] };
                uint32_t b1[2] = { t[2], t[3] };
                mma16816h(sa[2 * np],     qf[ks], b0);
                mma16816h(sa[2 * np + 1], qf[ks], b1);
            }
        }

        if (kb == qb) {
            int i0 = wid * 16 + (lane >> 2);
            int i1 = i0 + 8;
            #pragma unroll
            for (int nt = 0; nt < 8; nt++) {
                int j = nt * 8 + (lane & 3) * 2;
                if (j     > i0) sa[nt][0] = -1e30f;
                if (j + 1 > i0) sa[nt][1] = -1e30f;
                if (j     > i1) sa[nt][2] = -1e30f;
                if (j + 1 > i1) sa[nt][3] = -1e30f;
            }
        }

        float mx0 = -1e30f, mx1 = -1e30f;
        #pragma unroll
        for (int nt = 0; nt < 8; nt++) {
            mx0 = fmaxf(mx0, fmaxf(sa[nt][0], sa[nt][1]));
            mx1 = fmaxf(mx1, fmaxf(sa[nt][2], sa[nt][3]));
        }
        mx0 = fmaxf(mx0, __shfl_xor_sync(0xffffffffu, mx0, 1));
        mx0 = fmaxf(mx0, __shfl_xor_sync(0xffffffffu, mx0, 2));
        mx1 = fmaxf(mx1, __shfl_xor_sync(0xffffffffu, mx1, 1));
        mx1 = fmaxf(mx1, __shfl_xor_sync(0xffffffffu, mx1, 2));
        float mn0 = fmaxf(m0, mx0), mn1 = fmaxf(m1, mx1);
        float a0 = __expf(m0 - mn0), a1 = __expf(m1 - mn1);
        m0 = mn0; m1 = mn1;

        float lp0 = 0.f, lp1 = 0.f;
        #pragma unroll
        for (int nt = 0; nt < 8; nt++) {
            sa[nt][0] = __expf(sa[nt][0] - mn0);
            sa[nt][1] = __expf(sa[nt][1] - mn0);
            sa[nt][2] = __expf(sa[nt][2] - mn1);
            sa[nt][3] = __expf(sa[nt][3] - mn1);
            lp0 += sa[nt][0] + sa[nt][1];
            lp1 += sa[nt][2] + sa[nt][3];
        }
        lp0 += __shfl_xor_sync(0xffffffffu, lp0, 1);
        lp0 += __shfl_xor_sync(0xffffffffu, lp0, 2);
        lp1 += __shfl_xor_sync(0xffffffffu, lp1, 1);
        lp1 += __shfl_xor_sync(0xffffffffu, lp1, 2);
        l0 = l0 * a0 + lp0;
        l1 = l1 * a1 + lp1;

        #pragma unroll
        for (int dt = 0; dt < 10; dt++) {
            oa[dt][0] *= a0; oa[dt][1] *= a0;
            oa[dt][2] *= a1; oa[dt][3] *= a1;
        }

        uint32_t pf[4][4];
        #pragma unroll
        for (int kt = 0; kt < 4; kt++) {
            pf[kt][0] = h2u(sa[2 * kt][0],     sa[2 * kt][1]);
            pf[kt][1] = h2u(sa[2 * kt][2],     sa[2 * kt][3]);
            pf[kt][2] = h2u(sa[2 * kt + 1][0], sa[2 * kt + 1][1]);
            pf[kt][3] = h2u(sa[2 * kt + 1][2], sa[2 * kt + 1][3]);
        }

        #pragma unroll
        for (int kt = 0; kt < 4; kt++) {
            #pragma unroll
            for (int dp = 0; dp < 5; dp++) {
                uint32_t t[4];
                ldsm4t(t, SV + TOFF(kt * 16 + vrow, dp * 16 + vcol));
                uint32_t b0[2] = { t[0], t[1] };
                uint32_t b1[2] = { t[2], t[3] };
                mma16816h(oa[2 * dp],     pf[kt], b0);
                mma16816h(oa[2 * dp + 1], pf[kt], b1);
            }
        }
        __syncthreads();
    }

    float inv0 = 1.f / l0, inv1 = 1.f / l1;
    int r0 = q0 + wid * 16 + (lane >> 2);
    int dc = (lane & 3) * 2;
    #pragma unroll
    for (int dt = 0; dt < 10; dt++) {
        int d = dt * 8 + dc;
        __half2* p0 = (__half2*)(att + (size_t)r0 * NEMBD + h * HDIM + d);
        __half2* p1 = (__half2*)(att + (size_t)(r0 + 8) * NEMBD + h * HDIM + d);
        *p0 = __floats2half2_rn(oa[dt][0] * inv0, oa[dt][1] * inv0);
        *p1 = __floats2half2_rn(oa[dt][2] * inv1, oa[dt][3] * inv1);
    }
}

// ---------------------------------------------------------------------------
// Launch
// ---------------------------------------------------------------------------
extern "C" void kernel_launch(void* const* d_in, const int* in_sizes, int n_in,
                              void* d_out, int out_size) {
    const float* hidden = (const float*)d_in[0];
    const float* Wqkv_w = (const float*)d_in[1];
    const float* Wqkv_b = (const float*)d_in[2];
    const float* out_w  = (const float*)d_in[3];
    const float* out_b  = (const float*)d_in[4];
    const float* cosT   = (const float*)d_in[5];
    const float* sinT   = (const float*)d_in[6];
    float* out = (float*)d_out;

    float* qkv;
    cudaGetSymbolAddress((void**)&qkv, g_qkv);
    __half *Ha, *Ca, *Qh, *Kh, *Vh;
    cudaGetSymbolAddress((void**)&Ha, g_Ha);
    cudaGetSymbolAddress((void**)&Ca, g_Ca);
    cudaGetSymbolAddress((void**)&Qh, g_Qh);
    cudaGetSymbolAddress((void**)&Kh, g_Kh);
    cudaGetSymbolAddress((void**)&Vh, g_Vh);

    cudaFuncSetAttribute(gemm_fused<4>, cudaFuncAttributeMaxDynamicSharedMemorySize,
                         GEMM_SMEM_MT4);
    cudaFuncSetAttribute(gemm_fused<2>, cudaFuncAttributeMaxDynamicSharedMemorySize,
                         GEMM_SMEM_MT2);
    cudaFuncSetAttribute(flash_fp16, cudaFuncAttributeMaxDynamicSharedMemorySize,
                         FA_SMEM);

    // Truncate activations to fp16
    {
        int n4 = SEQ * NEMBD / 4;
        cvt_trunc<<<(n4 + 255) / 256, 256>>>(hidden, Ha, n4);
    }

    // 1) QKV = H @ Wqkv^T + b  (fused weight split, BM=128)
    {
        dim3 grid(OPSIZE / 128, SEQ / 128);
        gemm_fused<4><<<grid, 256, GEMM_SMEM_MT4>>>(Ha, Wqkv_w, Wqkv_b, qkv,
                                                    SEQ, OPSIZE, NEMBD);
    }

    // 2) RoPE + fp16 pack (head-major)
    {
        int total = SEQ * NHEAD * HDIM;
        rope_pack<<<(total + 255) / 256, 256>>>(qkv, cosT, sinT, Qh, Kh, Vh);
    }

    // 3) HMMA causal flash attention -> fp16 att
    {
        dim3 grid(SEQ / 64, NHEAD);
        flash_fp16<<<grid, 128, FA_SMEM>>>(Qh, Kh, Vh, Ca);
    }

    // 4) out = att @ out_w^T + out_b  (fused weight split, BM=64 for waves)
    {
        dim3 grid(NEMBD / 128, SEQ / 64);
        gemm_fused<2><<<grid, 256, GEMM_SMEM_MT2>>>(Ca, out_w, out_b, out,
                                                    SEQ, NEMBD, NEMBD);
    }
}

// round 14
// speedup vs baseline: 1.2245x; 1.2245x over previous
#include <cuda_runtime.h>
#include <cuda_fp16.h>
#include <math.h>
#include <stdint.h>

// Problem constants
#define SEQ     2048
#define NEMBD   2560
#define NHEAD   32
#define HDIM    80
#define RD      32
#define OPSIZE  7680   // 3 * NEMBD

// ---------------------------------------------------------------------------
// Static device scratch (allocation-free per harness rules)
// ---------------------------------------------------------------------------
__device__ float g_qkv[SEQ * OPSIZE];
__device__ __half g_Ha[SEQ * NEMBD];                          // hidden, fp16
__device__ __half g_Wh[OPSIZE * NEMBD], g_Wl[OPSIZE * NEMBD]; // Wqkv hi/lo
__device__ __half g_Ca[SEQ * NEMBD];                          // att out, fp16
__device__ __half g_Oh[NEMBD * NEMBD], g_Ol[NEMBD * NEMBD];   // out_w hi/lo
__device__ __half g_Qh[NHEAD * SEQ * HDIM];                   // head-major
__device__ __half g_Kh[NHEAD * SEQ * HDIM];
__device__ __half g_Vh[NHEAD * SEQ * HDIM];

// ---------------------------------------------------------------------------
// Helpers (base-target instructions only: cp.async / ldmatrix / mma.sync)
// ---------------------------------------------------------------------------
__device__ __forceinline__ uint32_t smem_u32(const void* p) {
    uint32_t a;
    asm("{ .reg .u64 t; cvta.to.shared.u64 t, %1; cvt.u32.u64 %0, t; }"
        : "=r"(a) : "l"(p));
    return a;
}
#define SWZ128(o) ((o) ^ (((o) >> 3) & 0x70))
// Padded-atom tile offset: rows of 128 fp16 logical cols, atoms 8r x 64c
#define TOFF(r, c) ((((r) >> 3) * 2048) + ((((c) >> 6)) << 10) + \
                    SWZ128((((r) & 7) << 7) + (((c) & 63) << 1)))

__device__ __forceinline__ void cp_async16(uint32_t s, const void* g) {
    asm volatile("cp.async.cg.shared.global [%0], [%1], 16;\n" :: "r"(s), "l"(g));
}

__device__ __forceinline__ void ldsm4(uint32_t* r, uint32_t a) {
    asm volatile("ldmatrix.sync.aligned.m8n8.x4.shared.b16 {%0,%1,%2,%3}, [%4];"
        : "=r"(r[0]), "=r"(r[1]), "=r"(r[2]), "=r"(r[3]) : "r"(a));
}
__device__ __forceinline__ void ldsm4t(uint32_t* r, uint32_t a) {
    asm volatile("ldmatrix.sync.aligned.m8n8.x4.trans.shared.b16 {%0,%1,%2,%3}, [%4];"
        : "=r"(r[0]), "=r"(r[1]), "=r"(r[2]), "=r"(r[3]) : "r"(a));
}

__device__ __forceinline__ void mma16816h(float* d, const uint32_t* a, const uint32_t* b) {
    asm volatile(
        "mma.sync.aligned.m16n8k16.row.col.f32.f16.f16.f32 "
        "{%0,%1,%2,%3}, {%4,%5,%6,%7}, {%8,%9}, {%0,%1,%2,%3};"
        : "+f"(d[0]), "+f"(d[1]), "+f"(d[2]), "+f"(d[3])
        : "r"(a[0]), "r"(a[1]), "r"(a[2]), "r"(a[3]), "r"(b[0]), "r"(b[1]));
}

__device__ __forceinline__ uint32_t h2u(float a, float b) {
    __half2 h = __floats2half2_rn(a, b);
    return *(uint32_t*)&h;
}

// ---------------------------------------------------------------------------
// fp32 -> fp16 truncate (activations)
// ---------------------------------------------------------------------------
__global__ void cvt_trunc(const float* __restrict__ x,
                          __half* __restrict__ h, int n4) {
    int i = blockIdx.x * blockDim.x + threadIdx.x;
    if (i >= n4) return;
    float4 v = ((const float4*)x)[i];
    __half2* hp = (__half2*)(h + i * 4);
    hp[0] = __floats2half2_rn(v.x, v.y);
    hp[1] = __floats2half2_rn(v.z, v.w);
}

// ---------------------------------------------------------------------------
// fp32 -> fp16 hi/lo split (weights)
// ---------------------------------------------------------------------------
__global__ void cvt_split16(const float* __restrict__ x,
                            __half* __restrict__ hi,
                            __half* __restrict__ lo, int n4) {
    int i = blockIdx.x * blockDim.x + threadIdx.x;
    if (i >= n4) return;
    float4 v = ((const float4*)x)[i];
    __half h0 = __float2half_rn(v.x);
    __half h1 = __float2half_rn(v.y);
    __half h2 = __float2half_rn(v.z);
    __half h3 = __float2half_rn(v.w);
    __half l0 = __float2half_rn(v.x - __half2float(h0));
    __half l1 = __float2half_rn(v.y - __half2float(h1));
    __half l2 = __float2half_rn(v.z - __half2float(h2));
    __half l3 = __float2half_rn(v.w - __half2float(h3));
    __half2* hp = (__half2*)(hi + i * 4);
    __half2* lp = (__half2*)(lo + i * 4);
    hp[0] = __half2(h0, h1); hp[1] = __half2(h2, h3);
    lp[0] = __half2(l0, l1); lp[1] = __half2(l2, l3);
}

// ---------------------------------------------------------------------------
// HMMA fp16 2-product GEMM:  C[m,n] = sum_k A[m,k]*B[n,k] + bias[n]
// A fp16-truncated, B split hi/lo: C = A*Bh + A*Bl.
// Tile: BM = MT*32 (MT=4 -> 128, MT=2 -> 64), BN=128, BK=64, SW128 smem,
// 3-stage cp.async pipeline (single barrier per chunk).
// 8 warps (2 x 4), warp tile (MT*16) x 32.
// ---------------------------------------------------------------------------
template<int MT>
__global__ __launch_bounds__(256, 1)
void gemm_fp16(const __half* __restrict__ Ah,
               const __half* __restrict__ Bh, const __half* __restrict__ Bl,
               const float* __restrict__ bias, float* __restrict__ C,
               int M, int N, int K) {
    extern __shared__ char sm[];
    const uint32_t smb = smem_u32(sm);
    constexpr int ATILE = MT * 32 * 128;           // A stage bytes
    constexpr int OBH = ATILE;
    constexpr int OBL = ATILE + 16384;
    constexpr int SBF = ATILE + 32768;             // stage stride

    const int tid  = threadIdx.x;
    const int lane = tid & 31;
    const int wid  = tid >> 5;
    const int wm   = wid >> 2;
    const int wn   = wid & 3;
    const int m0 = blockIdx.y * (MT * 32);
    const int n0 = blockIdx.x * 128;
    const int NC = K / 64;

    const __half* Ag = Ah + (size_t)m0 * K;
    const __half* Bgh = Bh + (size_t)n0 * K;
    const __half* Bgl = Bl + (size_t)n0 * K;

    float acc[MT][4][4];
    #pragma unroll
    for (int mt = 0; mt < MT; mt++)
        #pragma unroll
        for (int nt = 0; nt < 4; nt++)
            #pragma unroll
            for (int q = 0; q < 4; q++) acc[mt][nt][q] = 0.f;

    auto load_stage = [&](int c) {
        const uint32_t stg = smb + (c % 3) * SBF;
        const int k0 = c * 64;
        #pragma unroll
        for (int i = 0; i < MT; i++) {
            int id = tid + i * 256;
            int r = id >> 3, cc = id & 7;
            cp_async16(stg + SWZ128((uint32_t)(r * 128 + cc * 16)),
                       Ag + (size_t)r * K + k0 + cc * 8);
        }
        #pragma unroll
        for (int i = 0; i < 4; i++) {
            int id = tid + i * 256;
            int r = id >> 3, cc = id & 7;
            uint32_t so = SWZ128((uint32_t)(r * 128 + cc * 16));
            size_t go = (size_t)r * K + k0 + cc * 8;
            cp_async16(stg + OBH + so, Bgh + go);
            cp_async16(stg + OBL + so, Bgl + go);
        }
        asm volatile("cp.async.commit_group;" ::: "memory");
    };

    load_stage(0);
    load_stage(1);

    const int arow = wm * (MT * 16) + (lane & 7) + ((lane >> 3) & 1) * 8;
    const int akb  = (lane >> 4) * 16;
    const int brow = wn * 32 + (lane >> 4) * 8 + (lane & 7);
    const int bkb  = ((lane >> 3) & 1) * 16;

    for (int c = 0; c < NC; c++) {
        // Ensure chunk c is resident (allow chunk c+1 to stay in flight)
        if (c + 1 < NC) asm volatile("cp.async.wait_group 1;" ::: "memory");
        else            asm volatile("cp.async.wait_group 0;" ::: "memory");
        __syncthreads();   // all warps done with stage (c-1): safe to overwrite (c+2)%3
        if (c + 2 < NC) load_stage(c + 2);

        const uint32_t stg = smb + (c % 3) * SBF;
        #pragma unroll
        for (int ks = 0; ks < 4; ks++) {
            uint32_t ah[MT][4], bh[4][2], bl[4][2];
            #pragma unroll
            for (int mt = 0; mt < MT; mt++) {
                uint32_t so = SWZ128((uint32_t)((arow + mt * 16) * 128 + ks * 32 + akb));
                ldsm4(ah[mt], stg + so);
            }
            #pragma unroll
            for (int jj = 0; jj < 2; jj++) {
                uint32_t so = SWZ128((uint32_t)((brow + jj * 16) * 128 + ks * 32 + bkb));
                uint32_t t[4];
                ldsm4(t, stg + OBH + so);
                bh[jj * 2][0] = t[0]; bh[jj * 2][1] = t[1];
                bh[jj * 2 + 1][0] = t[2]; bh[jj * 2 + 1][1] = t[3];
                ldsm4(t, stg + OBL + so);
                bl[jj * 2][0] = t[0]; bl[jj * 2][1] = t[1];
                bl[jj * 2 + 1][0] = t[2]; bl[jj * 2 + 1][1] = t[3];
            }
            #pragma unroll
            for (int mt = 0; mt < MT; mt++)
                #pragma unroll
                for (int nt = 0; nt < 4; nt++)
                    mma16816h(acc[mt][nt], ah[mt], bh[nt]);
            #pragma unroll
            for (int mt = 0; mt < MT; mt++)
                #pragma unroll
                for (int nt = 0; nt < 4; nt++)
                    mma16816h(acc[mt][nt], ah[mt], bl[nt]);
        }
    }

    // Epilogue: bias add + store
    const int rb = m0 + wm * (MT * 16) + (lane >> 2);
    const int cb = n0 + wn * 32 + (lane & 3) * 2;
    #pragma unroll
    for (int mt = 0; mt < MT; mt++) {
        #pragma unroll
        for (int nt = 0; nt < 4; nt++) {
            int r0 = rb + mt * 16;
            int cc = cb + nt * 8;
            float2 b = *(const float2*)(bias + cc);
            float2 v0, v1;
            v0.x = acc[mt][nt][0] + b.x; v0.y = acc[mt][nt][1] + b.y;
            v1.x = acc[mt][nt][2] + b.x; v1.y = acc[mt][nt][3] + b.y;
            *(float2*)(C + (size_t)r0 * N + cc)       = v0;
            *(float2*)(C + (size_t)(r0 + 8) * N + cc) = v1;
        }
    }
}

#define GEMM_SMEM_MT4 (3 * (16384 + 32768))   // 147456
#define GEMM_SMEM_MT2 (3 * (8192 + 32768))    // 122880

// ---------------------------------------------------------------------------
// Fused RoPE (no sign flip) + fp16 pack to head-major [NHEAD][SEQ][80].
// Q pre-scaled by 1/sqrt(80).
// ---------------------------------------------------------------------------
__global__ void rope_pack(const float* __restrict__ qkv,
                          const float* __restrict__ cosT,
                          const float* __restrict__ sinT,
                          __half* __restrict__ Qh, __half* __restrict__ Kh,
                          __half* __restrict__ Vh) {
    int idx = blockIdx.x * blockDim.x + threadIdx.x;
    if (idx >= SEQ * NHEAD * HDIM) return;
    int d  = idx % HDIM;
    int th = idx / HDIM;
    int h  = th & 31;
    int t  = th >> 5;

    const float* base = qkv + (size_t)t * OPSIZE + h * HDIM;
    float q = base[d];
    float k = base[NEMBD + d];
    float v = base[2 * NEMBD + d];
    if (d < RD) {
        float c = cosT[t * RD + d];
        float s = sinT[t * RD + d];
        int dp = (d < 16) ? d + 16 : d - 16;
        q = q * c + base[dp] * s;
        k = k * c + base[NEMBD + dp] * s;
    }
    size_t o = ((size_t)h * SEQ + t) * HDIM + d;
    Qh[o] = __float2half(q * 0.11180339887498948f);
    Kh[o] = __float2half(k);
    Vh[o] = __float2half(v);
}

// ---------------------------------------------------------------------------
// HMMA fp16 flash attention (causal). Grid (qb, head), 128 threads (4 warps).
// BQ = BK = 64. Warp owns 16 q-rows. Smem: Q 16K + 2 stages x (K 16K + V 16K).
// Writes O directly as fp16 into att[t][h*80+d] (GEMM2 A operand).
// ---------------------------------------------------------------------------
#define FA_SMEM (16384 + 2 * 32768)   // 81920

__global__ __launch_bounds__(128, 2)
void flash_fp16(const __half* __restrict__ Qh, const __half* __restrict__ Kh,
                const __half* __restrict__ Vh, __half* __restrict__ att) {
    extern __shared__ char sm[];
    const uint32_t smb = smem_u32(sm);
    const int h = blockIdx.y;
    const int qb = blockIdx.x;
    const int q0 = qb * 64;
    const int tid = threadIdx.x;
    const int lane = tid & 31;
    const int wid = tid >> 5;

    const __half* Qg = Qh + ((size_t)h * SEQ + q0) * HDIM;
    const __half* Kg = Kh + (size_t)h * SEQ * HDIM;
    const __half* Vg = Vh + (size_t)h * SEQ * HDIM;

    const uint32_t SQ = smb;

    #pragma unroll
    for (int i = 0; i < 5; i++) {
        int id = tid + i * 128;
        int r = id / 10, c = id - r * 10;
        cp_async16(SQ + TOFF(r, c * 8), Qg + r * HDIM + c * 8);
    }
    asm volatile("cp.async.commit_group;" ::: "memory");

    auto load_kv = [&](int kb, int s) {
        const __half* kg = Kg + (size_t)kb * 64 * HDIM;
        const __half* vg = Vg + (size_t)kb * 64 * HDIM;
        uint32_t SK = smb + 16384 + s * 32768;
        uint32_t SV = SK + 16384;
        #pragma unroll
        for (int i = 0; i < 5; i++) {
            int id = tid + i * 128;
            int r = id / 10, c = id - r * 10;
            uint32_t o = TOFF(r, c * 8);
            cp_async16(SK + o, kg + r * HDIM + c * 8);
            cp_async16(SV + o, vg + r * HDIM + c * 8);
        }
        asm volatile("cp.async.commit_group;" ::: "memory");
    };

    load_kv(0, 0);
    asm volatile("cp.async.wait_group 0;" ::: "memory");
    __syncthreads();

    uint32_t qf[5][4];
    {
        int row = wid * 16 + (lane & 7) + ((lane >> 3) & 1) * 8;
        #pragma unroll
        for (int ks = 0; ks < 5; ks++) {
            int col = ks * 16 + (lane >> 4) * 8;
            ldsm4(qf[ks], SQ + TOFF(row, col));
        }
    }

    float m0 = -1e30f, m1 = -1e30f, l0 = 0.f, l1 = 0.f;
    float oa[10][4];
    #pragma unroll
    for (int dt = 0; dt < 10; dt++)
        #pragma unroll
        for (int q = 0; q < 4; q++) oa[dt][q] = 0.f;

    const int krow = (lane >> 4) * 8 + (lane & 7);
    const int kcol = ((lane >> 3) & 1) * 8;
    const int vrow = (lane & 7) + ((lane >> 3) & 1) * 8;
    const int vcol = (lane >> 4) * 8;

    for (int kb = 0; kb <= qb; kb++) {
        const int s = kb & 1;
        if (kb < qb) {
            load_kv(kb + 1, s ^ 1);
            asm volatile("cp.async.wait_group 1;" ::: "memory");
        } else {
            asm volatile("cp.async.wait_group 0;" ::: "memory");
        }
        __syncthreads();
        const uint32_t SK = smb + 16384 + s * 32768;
        const uint32_t SV = SK + 16384;

        float sa[8][4];
        #pragma unroll
        for (int nt = 0; nt < 8; nt++)
            #pragma unroll
            for (int q = 0; q < 4; q++) sa[nt][q] = 0.f;

        #pragma unroll
        for (int ks = 0; ks < 5; ks++) {
            int col = ks * 16 + kcol;
            #pragma unroll
            for (int np = 0; np < 4; np++) {
                uint32_t t[4];
                ldsm4(t, SK + TOFF(np * 16 + krow, col));
                uint32_t b0[2] = { t[0], t[1] };
                uint32_t b1[2] = { t[2], t[3] };
                mma16816h(sa[2 * np],     qf[ks], b0);
                mma16816h(sa[2 * np + 1], qf[ks], b1);
            }
        }

        if (kb == qb) {
            int i0 = wid * 16 + (lane >> 2);
            int i1 = i0 + 8;
            #pragma unroll
            for (int nt = 0; nt < 8; nt++) {
                int j = nt * 8 + (lane & 3) * 2;
                if (j     > i0) sa[nt][0] = -1e30f;
                if (j + 1 > i0) sa[nt][1] = -1e30f;
                if (j     > i1) sa[nt][2] = -1e30f;
                if (j + 1 > i1) sa[nt][3] = -1e30f;
            }
        }

        float mx0 = -1e30f, mx1 = -1e30f;
        #pragma unroll
        for (int nt = 0; nt < 8; nt++) {
            mx0 = fmaxf(mx0, fmaxf(sa[nt][0], sa[nt][1]));
            mx1 = fmaxf(mx1, fmaxf(sa[nt][2], sa[nt][3]));
        }
        mx0 = fmaxf(mx0, __shfl_xor_sync(0xffffffffu, mx0, 1));
        mx0 = fmaxf(mx0, __shfl_xor_sync(0xffffffffu, mx0, 2));
        mx1 = fmaxf(mx1, __shfl_xor_sync(0xffffffffu, mx1, 1));
        mx1 = fmaxf(mx1, __shfl_xor_sync(0xffffffffu, mx1, 2));
        float mn0 = fmaxf(m0, mx0), mn1 = fmaxf(m1, mx1);
        float a0 = __expf(m0 - mn0), a1 = __expf(m1 - mn1);
        m0 = mn0; m1 = mn1;

        float lp0 = 0.f, lp1 = 0.f;
        #pragma unroll
        for (int nt = 0; nt < 8; nt++) {
            sa[nt][0] = __expf(sa[nt][0] - mn0);
            sa[nt][1] = __expf(sa[nt][1] - mn0);
            sa[nt][2] = __expf(sa[nt][2] - mn1);
            sa[nt][3] = __expf(sa[nt][3] - mn1);
            lp0 += sa[nt][0] + sa[nt][1];
            lp1 += sa[nt][2] + sa[nt][3];
        }
        lp0 += __shfl_xor_sync(0xffffffffu, lp0, 1);
        lp0 += __shfl_xor_sync(0xffffffffu, lp0, 2);
        lp1 += __shfl_xor_sync(0xffffffffu, lp1, 1);
        lp1 += __shfl_xor_sync(0xffffffffu, lp1, 2);
        l0 = l0 * a0 + lp0;
        l1 = l1 * a1 + lp1;

        #pragma unroll
        for (int dt = 0; dt < 10; dt++) {
            oa[dt][0] *= a0; oa[dt][1] *= a0;
            oa[dt][2] *= a1; oa[dt][3] *= a1;
        }

        uint32_t pf[4][4];
        #pragma unroll
        for (int kt = 0; kt < 4; kt++) {
            pf[kt][0] = h2u(sa[2 * kt][0],     sa[2 * kt][1]);
            pf[kt][1] = h2u(sa[2 * kt][2],     sa[2 * kt][3]);
            pf[kt][2] = h2u(sa[2 * kt + 1][0], sa[2 * kt + 1][1]);
            pf[kt][3] = h2u(sa[2 * kt + 1][2], sa[2 * kt + 1][3]);
        }

        #pragma unroll
        for (int kt = 0; kt < 4; kt++) {
            #pragma unroll
            for (int dp = 0; dp < 5; dp++) {
                uint32_t t[4];
                ldsm4t(t, SV + TOFF(kt * 16 + vrow, dp * 16 + vcol));
                uint32_t b0[2] = { t[0], t[1] };
                uint32_t b1[2] = { t[2], t[3] };
                mma16816h(oa[2 * dp],     pf[kt], b0);
                mma16816h(oa[2 * dp + 1], pf[kt], b1);
            }
        }
        __syncthreads();
    }

    float inv0 = 1.f / l0, inv1 = 1.f / l1;
    int r0 = q0 + wid * 16 + (lane >> 2);
    int dc = (lane & 3) * 2;
    #pragma unroll
    for (int dt = 0; dt < 10; dt++) {
        int d = dt * 8 + dc;
        __half2* p0 = (__half2*)(att + (size_t)r0 * NEMBD + h * HDIM + d);
        __half2* p1 = (__half2*)(att + (size_t)(r0 + 8) * NEMBD + h * HDIM + d);
        *p0 = __floats2half2_rn(oa[dt][0] * inv0, oa[dt][1] * inv0);
        *p1 = __floats2half2_rn(oa[dt][2] * inv1, oa[dt][3] * inv1);
    }
}

// ---------------------------------------------------------------------------
// Launch
// ---------------------------------------------------------------------------
extern "C" void kernel_launch(void* const* d_in, const int* in_sizes, int n_in,
                              void* d_out, int out_size) {
    const float* hidden = (const float*)d_in[0];
    const float* Wqkv_w = (const float*)d_in[1];
    const float* Wqkv_b = (const float*)d_in[2];
    const float* out_w  = (const float*)d_in[3];
    const float* out_b  = (const float*)d_in[4];
    const float* cosT   = (const float*)d_in[5];
    const float* sinT   = (const float*)d_in[6];
    float* out = (float*)d_out;

    float* qkv;
    cudaGetSymbolAddress((void**)&qkv, g_qkv);
    __half *Ha, *Wh, *Wl, *Ca, *Oh, *Ol, *Qh, *Kh, *Vh;
    cudaGetSymbolAddress((void**)&Ha, g_Ha);
    cudaGetSymbolAddress((void**)&Wh, g_Wh); cudaGetSymbolAddress((void**)&Wl, g_Wl);
    cudaGetSymbolAddress((void**)&Ca, g_Ca);
    cudaGetSymbolAddress((void**)&Oh, g_Oh); cudaGetSymbolAddress((void**)&Ol, g_Ol);
    cudaGetSymbolAddress((void**)&Qh, g_Qh);
    cudaGetSymbolAddress((void**)&Kh, g_Kh);
    cudaGetSymbolAddress((void**)&Vh, g_Vh);

    cudaFuncSetAttribute(gemm_fp16<4>, cudaFuncAttributeMaxDynamicSharedMemorySize,
                         GEMM_SMEM_MT4);
    cudaFuncSetAttribute(gemm_fp16<2>, cudaFuncAttributeMaxDynamicSharedMemorySize,
                         GEMM_SMEM_MT2);
    cudaFuncSetAttribute(flash_fp16, cudaFuncAttributeMaxDynamicSharedMemorySize,
                         FA_SMEM);

    // Convert inputs
    {
        int n4 = SEQ * NEMBD / 4;
        cvt_trunc<<<(n4 + 255) / 256, 256>>>(hidden, Ha, n4);
        n4 = OPSIZE * NEMBD / 4;
        cvt_split16<<<(n4 + 255) / 256, 256>>>(Wqkv_w, Wh, Wl, n4);
    }

    // 1) QKV = H @ Wqkv^T + b  (BM=128, 3-stage)
    {
        dim3 grid(OPSIZE / 128, SEQ / 128);
        gemm_fp16<4><<<grid, 256, GEMM_SMEM_MT4>>>(Ha, Wh, Wl, Wqkv_b, qkv,
                                                   SEQ, OPSIZE, NEMBD);
    }

    // 2) RoPE + fp16 pack (head-major)
    {
        int total = SEQ * NHEAD * HDIM;
        rope_pack<<<(total + 255) / 256, 256>>>(qkv, cosT, sinT, Qh, Kh, Vh);
    }

    // 3) HMMA causal flash attention -> fp16 att
    {
        dim3 grid(SEQ / 64, NHEAD);
        flash_fp16<<<grid, 128, FA_SMEM>>>(Qh, Kh, Vh, Ca);
    }

    // 4) out = att @ out_w^T + out_b  (BM=64 for wave quantization, 3-stage)
    {
        int n4 = NEMBD * NEMBD / 4;
        cvt_split16<<<(n4 + 255) / 256, 256>>>(out_w, Oh, Ol, n4);
        dim3 grid(NEMBD / 128, SEQ / 64);
        gemm_fp16<2><<<grid, 256, GEMM_SMEM_MT2>>>(Ca, Oh, Ol, out_b, out,
                                                   SEQ, NEMBD, NEMBD);
    }
}

// round 16
// speedup vs baseline: 1.2344x; 1.0081x over previous
#include <cuda_runtime.h>
#include <cuda_fp16.h>
#include <math.h>
#include <stdint.h>

// Problem constants
#define SEQ     2048
#define NEMBD   2560
#define NHEAD   32
#define HDIM    80
#define RD      32
#define OPSIZE  7680   // 3 * NEMBD
#define NQB     (SEQ / 64)   // 32 q-tiles

// ---------------------------------------------------------------------------
// Static device scratch (allocation-free per harness rules)
// ---------------------------------------------------------------------------
__device__ float g_qkv[SEQ * OPSIZE];
__device__ __half g_Ha[SEQ * NEMBD];                          // hidden, fp16
__device__ __half g_Wh[OPSIZE * NEMBD], g_Wl[OPSIZE * NEMBD]; // Wqkv hi/lo
__device__ __half g_Ca[SEQ * NEMBD];                          // att out, fp16
__device__ __half g_Oh[NEMBD * NEMBD], g_Ol[NEMBD * NEMBD];   // out_w hi/lo
__device__ __half g_Qh[NHEAD * SEQ * HDIM];                   // head-major
__device__ __half g_Kh[NHEAD * SEQ * HDIM];
__device__ __half g_Vh[NHEAD * SEQ * HDIM];

// ---------------------------------------------------------------------------
// Helpers (base-target instructions only: cp.async / ldmatrix / mma.sync)
// ---------------------------------------------------------------------------
__device__ __forceinline__ uint32_t smem_u32(const void* p) {
    uint32_t a;
    asm("{ .reg .u64 t; cvta.to.shared.u64 t, %1; cvt.u32.u64 %0, t; }"
        : "=r"(a) : "l"(p));
    return a;
}
#define SWZ128(o) ((o) ^ (((o) >> 3) & 0x70))
// Padded-atom tile offset: rows of 128 fp16 logical cols, atoms 8r x 64c
#define TOFF(r, c) ((((r) >> 3) * 2048) + ((((c) >> 6)) << 10) + \
                    SWZ128((((r) & 7) << 7) + (((c) & 63) << 1)))

__device__ __forceinline__ void cp_async16(uint32_t s, const void* g) {
    asm volatile("cp.async.cg.shared.global [%0], [%1], 16;\n" :: "r"(s), "l"(g));
}

__device__ __forceinline__ void ldsm4(uint32_t* r, uint32_t a) {
    asm volatile("ldmatrix.sync.aligned.m8n8.x4.shared.b16 {%0,%1,%2,%3}, [%4];"
        : "=r"(r[0]), "=r"(r[1]), "=r"(r[2]), "=r"(r[3]) : "r"(a));
}
__device__ __forceinline__ void ldsm4t(uint32_t* r, uint32_t a) {
    asm volatile("ldmatrix.sync.aligned.m8n8.x4.trans.shared.b16 {%0,%1,%2,%3}, [%4];"
        : "=r"(r[0]), "=r"(r[1]), "=r"(r[2]), "=r"(r[3]) : "r"(a));
}

__device__ __forceinline__ void mma16816h(float* d, const uint32_t* a, const uint32_t* b) {
    asm volatile(
        "mma.sync.aligned.m16n8k16.row.col.f32.f16.f16.f32 "
        "{%0,%1,%2,%3}, {%4,%5,%6,%7}, {%8,%9}, {%0,%1,%2,%3};"
        : "+f"(d[0]), "+f"(d[1]), "+f"(d[2]), "+f"(d[3])
        : "r"(a[0]), "r"(a[1]), "r"(a[2]), "r"(a[3]), "r"(b[0]), "r"(b[1]));
}

__device__ __forceinline__ uint32_t h2u(float a, float b) {
    __half2 h = __floats2half2_rn(a, b);
    return *(uint32_t*)&h;
}

// ---------------------------------------------------------------------------
// fp32 -> fp16 truncate (activations)
// ---------------------------------------------------------------------------
__global__ void cvt_trunc(const float* __restrict__ x,
                          __half* __restrict__ h, int n4) {
    int i = blockIdx.x * blockDim.x + threadIdx.x;
    if (i >= n4) return;
    float4 v = ((const float4*)x)[i];
    __half2* hp = (__half2*)(h + i * 4);
    hp[0] = __floats2half2_rn(v.x, v.y);
    hp[1] = __floats2half2_rn(v.z, v.w);
}

// ---------------------------------------------------------------------------
// fp32 -> fp16 hi/lo split (weights)
// ---------------------------------------------------------------------------
__global__ void cvt_split16(const float* __restrict__ x,
                            __half* __restrict__ hi,
                            __half* __restrict__ lo, int n4) {
    int i = blockIdx.x * blockDim.x + threadIdx.x;
    if (i >= n4) return;
    float4 v = ((const float4*)x)[i];
    __half h0 = __float2half_rn(v.x);
    __half h1 = __float2half_rn(v.y);
    __half h2 = __float2half_rn(v.z);
    __half h3 = __float2half_rn(v.w);
    __half l0 = __float2half_rn(v.x - __half2float(h0));
    __half l1 = __float2half_rn(v.y - __half2float(h1));
    __half l2 = __float2half_rn(v.z - __half2float(h2));
    __half l3 = __float2half_rn(v.w - __half2float(h3));
    __half2* hp = (__half2*)(hi + i * 4);
    __half2* lp = (__half2*)(lo + i * 4);
    hp[0] = __half2(h0, h1); hp[1] = __half2(h2, h3);
    lp[0] = __half2(l0, l1); lp[1] = __half2(l2, l3);
}

// ---------------------------------------------------------------------------
// HMMA fp16 2-product GEMM (unchanged from R14):
//   C[m,n] = sum_k A[m,k]*B[n,k] + bias[n],  C = A*Bh + A*Bl.
// BM = MT*32, BN=128, BK=64, SW128 smem, 3-stage cp.async pipeline.
// ---------------------------------------------------------------------------
template<int MT>
__global__ __launch_bounds__(256, 1)
void gemm_fp16(const __half* __restrict__ Ah,
               const __half* __restrict__ Bh, const __half* __restrict__ Bl,
               const float* __restrict__ bias, float* __restrict__ C,
               int M, int N, int K) {
    extern __shared__ char sm[];
    const uint32_t smb = smem_u32(sm);
    constexpr int ATILE = MT * 32 * 128;
    constexpr int OBH = ATILE;
    constexpr int OBL = ATILE + 16384;
    constexpr int SBF = ATILE + 32768;

    const int tid  = threadIdx.x;
    const int lane = tid & 31;
    const int wid  = tid >> 5;
    const int wm   = wid >> 2;
    const int wn   = wid & 3;
    const int m0 = blockIdx.y * (MT * 32);
    const int n0 = blockIdx.x * 128;
    const int NC = K / 64;

    const __half* Ag = Ah + (size_t)m0 * K;
    const __half* Bgh = Bh + (size_t)n0 * K;
    const __half* Bgl = Bl + (size_t)n0 * K;

    float acc[MT][4][4];
    #pragma unroll
    for (int mt = 0; mt < MT; mt++)
        #pragma unroll
        for (int nt = 0; nt < 4; nt++)
            #pragma unroll
            for (int q = 0; q < 4; q++) acc[mt][nt][q] = 0.f;

    auto load_stage = [&](int c) {
        const uint32_t stg = smb + (c % 3) * SBF;
        const int k0 = c * 64;
        #pragma unroll
        for (int i = 0; i < MT; i++) {
            int id = tid + i * 256;
            int r = id >> 3, cc = id & 7;
            cp_async16(stg + SWZ128((uint32_t)(r * 128 + cc * 16)),
                       Ag + (size_t)r * K + k0 + cc * 8);
        }
        #pragma unroll
        for (int i = 0; i < 4; i++) {
            int id = tid + i * 256;
            int r = id >> 3, cc = id & 7;
            uint32_t so = SWZ128((uint32_t)(r * 128 + cc * 16));
            size_t go = (size_t)r * K + k0 + cc * 8;
            cp_async16(stg + OBH + so, Bgh + go);
            cp_async16(stg + OBL + so, Bgl + go);
        }
        asm volatile("cp.async.commit_group;" ::: "memory");
    };

    load_stage(0);
    load_stage(1);

    const int arow = wm * (MT * 16) + (lane & 7) + ((lane >> 3) & 1) * 8;
    const int akb  = (lane >> 4) * 16;
    const int brow = wn * 32 + (lane >> 4) * 8 + (lane & 7);
    const int bkb  = ((lane >> 3) & 1) * 16;

    for (int c = 0; c < NC; c++) {
        if (c + 1 < NC) asm volatile("cp.async.wait_group 1;" ::: "memory");
        else            asm volatile("cp.async.wait_group 0;" ::: "memory");
        __syncthreads();
        if (c + 2 < NC) load_stage(c + 2);

        const uint32_t stg = smb + (c % 3) * SBF;
        #pragma unroll
        for (int ks = 0; ks < 4; ks++) {
            uint32_t ah[MT][4], bh[4][2], bl[4][2];
            #pragma unroll
            for (int mt = 0; mt < MT; mt++) {
                uint32_t so = SWZ128((uint32_t)((arow + mt * 16) * 128 + ks * 32 + akb));
                ldsm4(ah[mt], stg + so);
            }
            #pragma unroll
            for (int jj = 0; jj < 2; jj++) {
                uint32_t so = SWZ128((uint32_t)((brow + jj * 16) * 128 + ks * 32 + bkb));
                uint32_t t[4];
                ldsm4(t, stg + OBH + so);
                bh[jj * 2][0] = t[0]; bh[jj * 2][1] = t[1];
                bh[jj * 2 + 1][0] = t[2]; bh[jj * 2 + 1][1] = t[3];
                ldsm4(t, stg + OBL + so);
                bl[jj * 2][0] = t[0]; bl[jj * 2][1] = t[1];
                bl[jj * 2 + 1][0] = t[2]; bl[jj * 2 + 1][1] = t[3];
            }
            #pragma unroll
            for (int mt = 0; mt < MT; mt++)
                #pragma unroll
                for (int nt = 0; nt < 4; nt++)
                    mma16816h(acc[mt][nt], ah[mt], bh[nt]);
            #pragma unroll
            for (int mt = 0; mt < MT; mt++)
                #pragma unroll
                for (int nt = 0; nt < 4; nt++)
                    mma16816h(acc[mt][nt], ah[mt], bl[nt]);
        }
    }

    const int rb = m0 + wm * (MT * 16) + (lane >> 2);
    const int cb = n0 + wn * 32 + (lane & 3) * 2;
    #pragma unroll
    for (int mt = 0; mt < MT; mt++) {
        #pragma unroll
        for (int nt = 0; nt < 4; nt++) {
            int r0 = rb + mt * 16;
            int cc = cb + nt * 8;
            float2 b = *(const float2*)(bias + cc);
            float2 v0, v1;
            v0.x = acc[mt][nt][0] + b.x; v0.y = acc[mt][nt][1] + b.y;
            v1.x = acc[mt][nt][2] + b.x; v1.y = acc[mt][nt][3] + b.y;
            *(float2*)(C + (size_t)r0 * N + cc)       = v0;
            *(float2*)(C + (size_t)(r0 + 8) * N + cc) = v1;
        }
    }
}

#define GEMM_SMEM_MT4 (3 * (16384 + 32768))   // 147456
#define GEMM_SMEM_MT2 (3 * (8192 + 32768))    // 122880

// ---------------------------------------------------------------------------
// Fused RoPE (no sign flip) + fp16 pack to head-major [NHEAD][SEQ][80].
// ---------------------------------------------------------------------------
__global__ void rope_pack(const float* __restrict__ qkv,
                          const float* __restrict__ cosT,
                          const float* __restrict__ sinT,
                          __half* __restrict__ Qh, __half* __restrict__ Kh,
                          __half* __restrict__ Vh) {
    int idx = blockIdx.x * blockDim.x + threadIdx.x;
    if (idx >= SEQ * NHEAD * HDIM) return;
    int d  = idx % HDIM;
    int th = idx / HDIM;
    int h  = th & 31;
    int t  = th >> 5;

    const float* base = qkv + (size_t)t * OPSIZE + h * HDIM;
    float q = base[d];
    float k = base[NEMBD + d];
    float v = base[2 * NEMBD + d];
    if (d < RD) {
        float c = cosT[t * RD + d];
        float s = sinT[t * RD + d];
        int dp = (d < 16) ? d + 16 : d - 16;
        q = q * c + base[dp] * s;
        k = k * c + base[NEMBD + dp] * s;
    }
    size_t o = ((size_t)h * SEQ + t) * HDIM + d;
    Qh[o] = __float2half(q * 0.11180339887498948f);
    Kh[o] = __float2half(k);
    Vh[o] = __float2half(v);
}

// ---------------------------------------------------------------------------
// HMMA fp16 flash attention (causal), work-balanced.
// Grid (NQB/2, NHEAD), 128 threads. CTA (p,h) processes q-tiles {p, NQB-1-p}
// sequentially: per-CTA work = (p+1) + (NQB-p) = NQB+1 tiles, uniform.
// Smem: Q 16K + 2 stages x (K 16K + V 16K). Output fp16 att[t][h*80+d].
// ---------------------------------------------------------------------------
#define FA_SMEM (16384 + 2 * 32768)   // 81920

__global__ __launch_bounds__(128, 2)
void flash_fp16(const __half* __restrict__ Qh, const __half* __restrict__ Kh,
                const __half* __restrict__ Vh, __half* __restrict__ att) {
    extern __shared__ char sm[];
    const uint32_t smb = smem_u32(sm);
    const int h = blockIdx.y;
    const int pair = blockIdx.x;
    const int tid = threadIdx.x;
    const int lane = tid & 31;
    const int wid = tid >> 5;

    const __half* Kg = Kh + (size_t)h * SEQ * HDIM;
    const __half* Vg = Vh + (size_t)h * SEQ * HDIM;
    const uint32_t SQ = smb;

    const int krow = (lane >> 4) * 8 + (lane & 7);
    const int kcol = ((lane >> 3) & 1) * 8;
    const int vrow = (lane & 7) + ((lane >> 3) & 1) * 8;
    const int vcol = (lane >> 4) * 8;

    auto load_kv = [&](int kb, int s) {
        const __half* kg = Kg + (size_t)kb * 64 * HDIM;
        const __half* vg = Vg + (size_t)kb * 64 * HDIM;
        uint32_t SK = smb + 16384 + s * 32768;
        uint32_t SV = SK + 16384;
        #pragma unroll
        for (int i = 0; i < 5; i++) {
            int id = tid + i * 128;
            int r = id / 10, c = id - r * 10;
            uint32_t o = TOFF(r, c * 8);
            cp_async16(SK + o, kg + r * HDIM + c * 8);
            cp_async16(SV + o, vg + r * HDIM + c * 8);
        }
        asm volatile("cp.async.commit_group;" ::: "memory");
    };

    #pragma unroll 1
    for (int half = 0; half < 2; half++) {
        const int qb = half ? (NQB - 1 - pair) : pair;
        const int q0 = qb * 64;
        const __half* Qg = Qh + ((size_t)h * SEQ + q0) * HDIM;

        // Load Q tile + KV tile 0
        #pragma unroll
        for (int i = 0; i < 5; i++) {
            int id = tid + i * 128;
            int r = id / 10, c = id - r * 10;
            cp_async16(SQ + TOFF(r, c * 8), Qg + r * HDIM + c * 8);
        }
        asm volatile("cp.async.commit_group;" ::: "memory");
        load_kv(0, 0);
        asm volatile("cp.async.wait_group 0;" ::: "memory");
        __syncthreads();

        uint32_t qf[5][4];
        {
            int row = wid * 16 + (lane & 7) + ((lane >> 3) & 1) * 8;
            #pragma unroll
            for (int ks = 0; ks < 5; ks++) {
                int col = ks * 16 + (lane >> 4) * 8;
                ldsm4(qf[ks], SQ + TOFF(row, col));
            }
        }

        float m0 = -1e30f, m1 = -1e30f, l0 = 0.f, l1 = 0.f;
        float oa[10][4];
        #pragma unroll
        for (int dt = 0; dt < 10; dt++)
            #pragma unroll
            for (int q = 0; q < 4; q++) oa[dt][q] = 0.f;

        for (int kb = 0; kb <= qb; kb++) {
            const int s = kb & 1;
            if (kb < qb) {
                load_kv(kb + 1, s ^ 1);
                asm volatile("cp.async.wait_group 1;" ::: "memory");
            } else {
                asm volatile("cp.async.wait_group 0;" ::: "memory");
            }
            __syncthreads();
            const uint32_t SK = smb + 16384 + s * 32768;
            const uint32_t SV = SK + 16384;

            float sa[8][4];
            #pragma unroll
            for (int nt = 0; nt < 8; nt++)
                #pragma unroll
                for (int q = 0; q < 4; q++) sa[nt][q] = 0.f;

            #pragma unroll
            for (int ks = 0; ks < 5; ks++) {
                int col = ks * 16 + kcol;
                #pragma unroll
                for (int np = 0; np < 4; np++) {
                    uint32_t t[4];
                    ldsm4(t, SK + TOFF(np * 16 + krow, col));
                    uint32_t b0[2] = { t[0], t[1] };
                    uint32_t b1[2] = { t[2], t[3] };
                    mma16816h(sa[2 * np],     qf[ks], b0);
                    mma16816h(sa[2 * np + 1], qf[ks], b1);
                }
            }

            if (kb == qb) {
                int i0 = wid * 16 + (lane >> 2);
                int i1 = i0 + 8;
                #pragma unroll
                for (int nt = 0; nt < 8; nt++) {
                    int j = nt * 8 + (lane & 3) * 2;
                    if (j     > i0) sa[nt][0] = -1e30f;
                    if (j + 1 > i0) sa[nt][1] = -1e30f;
                    if (j     > i1) sa[nt][2] = -1e30f;
                    if (j + 1 > i1) sa[nt][3] = -1e30f;
                }
            }

            float mx0 = -1e30f, mx1 = -1e30f;
            #pragma unroll
            for (int nt = 0; nt < 8; nt++) {
                mx0 = fmaxf(mx0, fmaxf(sa[nt][0], sa[nt][1]));
                mx1 = fmaxf(mx1, fmaxf(sa[nt][2], sa[nt][3]));
            }
            mx0 = fmaxf(mx0, __shfl_xor_sync(0xffffffffu, mx0, 1));
            mx0 = fmaxf(mx0, __shfl_xor_sync(0xffffffffu, mx0, 2));
            mx1 = fmaxf(mx1, __shfl_xor_sync(0xffffffffu, mx1, 1));
            mx1 = fmaxf(mx1, __shfl_xor_sync(0xffffffffu, mx1, 2));
            float mn0 = fmaxf(m0, mx0), mn1 = fmaxf(m1, mx1);
            float a0 = __expf(m0 - mn0), a1 = __expf(m1 - mn1);
            m0 = mn0; m1 = mn1;

            float lp0 = 0.f, lp1 = 0.f;
            #pragma unroll
            for (int nt = 0; nt < 8; nt++) {
                sa[nt][0] = __expf(sa[nt][0] - mn0);
                sa[nt][1] = __expf(sa[nt][1] - mn0);
                sa[nt][2] = __expf(sa[nt][2] - mn1);
                sa[nt][3] = __expf(sa[nt][3] - mn1);
                lp0 += sa[nt][0] + sa[nt][1];
                lp1 += sa[nt][2] + sa[nt][3];
            }
            lp0 += __shfl_xor_sync(0xffffffffu, lp0, 1);
            lp0 += __shfl_xor_sync(0xffffffffu, lp0, 2);
            lp1 += __shfl_xor_sync(0xffffffffu, lp1, 1);
            lp1 += __shfl_xor_sync(0xffffffffu, lp1, 2);
            l0 = l0 * a0 + lp0;
            l1 = l1 * a1 + lp1;

            #pragma unroll
            for (int dt = 0; dt < 10; dt++) {
                oa[dt][0] *= a0; oa[dt][1] *= a0;
                oa[dt][2] *= a1; oa[dt][3] *= a1;
            }

            uint32_t pf[4][4];
            #pragma unroll
            for (int kt = 0; kt < 4; kt++) {
                pf[kt][0] = h2u(sa[2 * kt][0],     sa[2 * kt][1]);
                pf[kt][1] = h2u(sa[2 * kt][2],     sa[2 * kt][3]);
                pf[kt][2] = h2u(sa[2 * kt + 1][0], sa[2 * kt + 1][1]);
                pf[kt][3] = h2u(sa[2 * kt + 1][2], sa[2 * kt + 1][3]);
            }

            #pragma unroll
            for (int kt = 0; kt < 4; kt++) {
                #pragma unroll
                for (int dp = 0; dp < 5; dp++) {
                    uint32_t t[4];
                    ldsm4t(t, SV + TOFF(kt * 16 + vrow, dp * 16 + vcol));
                    uint32_t b0[2] = { t[0], t[1] };
                    uint32_t b1[2] = { t[2], t[3] };
                    mma16816h(oa[2 * dp],     pf[kt], b0);
                    mma16816h(oa[2 * dp + 1], pf[kt], b1);
                }
            }
            __syncthreads();
        }

        // Normalize + write fp16 output
        float inv0 = 1.f / l0, inv1 = 1.f / l1;
        int r0 = q0 + wid * 16 + (lane >> 2);
        int dc = (lane & 3) * 2;
        #pragma unroll
        for (int dt = 0; dt < 10; dt++) {
            int d = dt * 8 + dc;
            __half2* p0 = (__half2*)(att + (size_t)r0 * NEMBD + h * HDIM + d);
            __half2* p1 = (__half2*)(att + (size_t)(r0 + 8) * NEMBD + h * HDIM + d);
            *p0 = __floats2half2_rn(oa[dt][0] * inv0, oa[dt][1] * inv0);
            *p1 = __floats2half2_rn(oa[dt][2] * inv1, oa[dt][3] * inv1);
        }
        __syncthreads();   // SQ / KV stages reused by next half
    }
}

// ---------------------------------------------------------------------------
// Launch
// ---------------------------------------------------------------------------
extern "C" void kernel_launch(void* const* d_in, const int* in_sizes, int n_in,
                              void* d_out, int out_size) {
    const float* hidden = (const float*)d_in[0];
    const float* Wqkv_w = (const float*)d_in[1];
    const float* Wqkv_b = (const float*)d_in[2];
    const float* out_w  = (const float*)d_in[3];
    const float* out_b  = (const float*)d_in[4];
    const float* cosT   = (const float*)d_in[5];
    const float* sinT   = (const float*)d_in[6];
    float* out = (float*)d_out;

    float* qkv;
    cudaGetSymbolAddress((void**)&qkv, g_qkv);
    __half *Ha, *Wh, *Wl, *Ca, *Oh, *Ol, *Qh, *Kh, *Vh;
    cudaGetSymbolAddress((void**)&Ha, g_Ha);
    cudaGetSymbolAddress((void**)&Wh, g_Wh); cudaGetSymbolAddress((void**)&Wl, g_Wl);
    cudaGetSymbolAddress((void**)&Ca, g_Ca);
    cudaGetSymbolAddress((void**)&Oh, g_Oh); cudaGetSymbolAddress((void**)&Ol, g_Ol);
    cudaGetSymbolAddress((void**)&Qh, g_Qh);
    cudaGetSymbolAddress((void**)&Kh, g_Kh);
    cudaGetSymbolAddress((void**)&Vh, g_Vh);

    cudaFuncSetAttribute(gemm_fp16<4>, cudaFuncAttributeMaxDynamicSharedMemorySize,
                         GEMM_SMEM_MT4);
    cudaFuncSetAttribute(gemm_fp16<2>, cudaFuncAttributeMaxDynamicSharedMemorySize,
                         GEMM_SMEM_MT2);
    cudaFuncSetAttribute(flash_fp16, cudaFuncAttributeMaxDynamicSharedMemorySize,
                         FA_SMEM);

    // Convert inputs
    {
        int n4 = SEQ * NEMBD / 4;
        cvt_trunc<<<(n4 + 255) / 256, 256>>>(hidden, Ha, n4);
        n4 = OPSIZE * NEMBD / 4;
        cvt_split16<<<(n4 + 255) / 256, 256>>>(Wqkv_w, Wh, Wl, n4);
    }

    // 1) QKV = H @ Wqkv^T + b  (BM=128, 3-stage)
    {
        dim3 grid(OPSIZE / 128, SEQ / 128);
        gemm_fp16<4><<<grid, 256, GEMM_SMEM_MT4>>>(Ha, Wh, Wl, Wqkv_b, qkv,
                                                   SEQ, OPSIZE, NEMBD);
    }

    // 2) RoPE + fp16 pack (head-major)
    {
        int total = SEQ * NHEAD * HDIM;
        rope_pack<<<(total + 255) / 256, 256>>>(qkv, cosT, sinT, Qh, Kh, Vh);
    }

    // 3) HMMA causal flash attention, work-balanced pairs -> fp16 att
    {
        dim3 grid(NQB / 2, NHEAD);
        flash_fp16<<<grid, 128, FA_SMEM>>>(Qh, Kh, Vh, Ca);
    }

    // 4) out = att @ out_w^T + out_b  (BM=64 for wave quantization, 3-stage)
    {
        int n4 = NEMBD * NEMBD / 4;
        cvt_split16<<<(n4 + 255) / 256, 256>>>(out_w, Oh, Ol, n4);
        dim3 grid(NEMBD / 128, SEQ / 64);
        gemm_fp16<2><<<grid, 256, GEMM_SMEM_MT2>>>(Ca, Oh, Ol, out_b, out,
                                                   SEQ, NEMBD, NEMBD);
    }
}

// round 17
// speedup vs baseline: 1.8004x; 1.4584x over previous
#include <cuda_runtime.h>
#include <cuda_fp16.h>
#include <math.h>
#include <stdint.h>

// Problem constants
#define SEQ     2048
#define NEMBD   2560
#define NHEAD   32
#define HDIM    80
#define RD      32
#define OPSIZE  7680   // 3 * NEMBD
#define NQB     (SEQ / 64)   // 32 q-tiles

// ---------------------------------------------------------------------------
// Static device scratch (allocation-free per harness rules)
// ---------------------------------------------------------------------------
__device__ float g_qkv[SEQ * OPSIZE];
__device__ __half g_Ha[SEQ * NEMBD];             // hidden, fp16
__device__ __half g_Wq[OPSIZE * NEMBD];          // Wqkv fp16
__device__ __half g_Ca[SEQ * NEMBD];             // att out, fp16
__device__ __half g_Ow[NEMBD * NEMBD];           // out_w fp16
__device__ __half g_Qh[NHEAD * SEQ * HDIM];      // head-major
__device__ __half g_Kh[NHEAD * SEQ * HDIM];
__device__ __half g_Vh[NHEAD * SEQ * HDIM];

// ---------------------------------------------------------------------------
// Helpers (base-target instructions only: cp.async / ldmatrix / mma.sync)
// ---------------------------------------------------------------------------
__device__ __forceinline__ uint32_t smem_u32(const void* p) {
    uint32_t a;
    asm("{ .reg .u64 t; cvta.to.shared.u64 t, %1; cvt.u32.u64 %0, t; }"
        : "=r"(a) : "l"(p));
    return a;
}
#define SWZ128(o) ((o) ^ (((o) >> 3) & 0x70))
// Padded-atom tile offset: rows of 128 fp16 logical cols, atoms 8r x 64c
#define TOFF(r, c) ((((r) >> 3) * 2048) + ((((c) >> 6)) << 10) + \
                    SWZ128((((r) & 7) << 7) + (((c) & 63) << 1)))

__device__ __forceinline__ void cp_async16(uint32_t s, const void* g) {
    asm volatile("cp.async.cg.shared.global [%0], [%1], 16;\n" :: "r"(s), "l"(g));
}

__device__ __forceinline__ void ldsm4(uint32_t* r, uint32_t a) {
    asm volatile("ldmatrix.sync.aligned.m8n8.x4.shared.b16 {%0,%1,%2,%3}, [%4];"
        : "=r"(r[0]), "=r"(r[1]), "=r"(r[2]), "=r"(r[3]) : "r"(a));
}
__device__ __forceinline__ void ldsm4t(uint32_t* r, uint32_t a) {
    asm volatile("ldmatrix.sync.aligned.m8n8.x4.trans.shared.b16 {%0,%1,%2,%3}, [%4];"
        : "=r"(r[0]), "=r"(r[1]), "=r"(r[2]), "=r"(r[3]) : "r"(a));
}

__device__ __forceinline__ void mma16816h(float* d, const uint32_t* a, const uint32_t* b) {
    asm volatile(
        "mma.sync.aligned.m16n8k16.row.col.f32.f16.f16.f32 "
        "{%0,%1,%2,%3}, {%4,%5,%6,%7}, {%8,%9}, {%0,%1,%2,%3};"
        : "+f"(d[0]), "+f"(d[1]), "+f"(d[2]), "+f"(d[3])
        : "r"(a[0]), "r"(a[1]), "r"(a[2]), "r"(a[3]), "r"(b[0]), "r"(b[1]));
}

__device__ __forceinline__ uint32_t h2u(float a, float b) {
    __half2 h = __floats2half2_rn(a, b);
    return *(uint32_t*)&h;
}

// ---------------------------------------------------------------------------
// fp32 -> fp16 truncate (activations and weights)
// ---------------------------------------------------------------------------
__global__ void cvt_trunc(const float* __restrict__ x,
                          __half* __restrict__ h, int n4) {
    int i = blockIdx.x * blockDim.x + threadIdx.x;
    if (i >= n4) return;
    float4 v = ((const float4*)x)[i];
    __half2* hp = (__half2*)(h + i * 4);
    hp[0] = __floats2half2_rn(v.x, v.y);
    hp[1] = __floats2half2_rn(v.z, v.w);
}

// ---------------------------------------------------------------------------
// HMMA fp16 single-product GEMM:  C[m,n] = sum_k A[m,k]*B[n,k] + bias[n]
// A, B both fp16 (RN-truncated). BM = MT*32, BN=128, BK=64, SW128 smem,
// 3-stage cp.async pipeline. 8 warps (2 x 4), warp tile (MT*16) x 32.
// ---------------------------------------------------------------------------
template<int MT>
__global__ __launch_bounds__(256, 1)
void gemm_fp16(const __half* __restrict__ Ah, const __half* __restrict__ Bh,
               const float* __restrict__ bias, float* __restrict__ C,
               int M, int N, int K) {
    extern __shared__ char sm[];
    const uint32_t smb = smem_u32(sm);
    constexpr int ATILE = MT * 32 * 128;
    constexpr int OBH = ATILE;
    constexpr int SBF = ATILE + 16384;

    const int tid  = threadIdx.x;
    const int lane = tid & 31;
    const int wid  = tid >> 5;
    const int wm   = wid >> 2;
    const int wn   = wid & 3;
    const int m0 = blockIdx.y * (MT * 32);
    const int n0 = blockIdx.x * 128;
    const int NC = K / 64;

    const __half* Ag = Ah + (size_t)m0 * K;
    const __half* Bg = Bh + (size_t)n0 * K;

    float acc[MT][4][4];
    #pragma unroll
    for (int mt = 0; mt < MT; mt++)
        #pragma unroll
        for (int nt = 0; nt < 4; nt++)
            #pragma unroll
            for (int q = 0; q < 4; q++) acc[mt][nt][q] = 0.f;

    auto load_stage = [&](int c) {
        const uint32_t stg = smb + (c % 3) * SBF;
        const int k0 = c * 64;
        #pragma unroll
        for (int i = 0; i < MT; i++) {
            int id = tid + i * 256;
            int r = id >> 3, cc = id & 7;
            cp_async16(stg + SWZ128((uint32_t)(r * 128 + cc * 16)),
                       Ag + (size_t)r * K + k0 + cc * 8);
        }
        #pragma unroll
        for (int i = 0; i < 4; i++) {
            int id = tid + i * 256;
            int r = id >> 3, cc = id & 7;
            cp_async16(stg + OBH + SWZ128((uint32_t)(r * 128 + cc * 16)),
                       Bg + (size_t)r * K + k0 + cc * 8);
        }
        asm volatile("cp.async.commit_group;" ::: "memory");
    };

    load_stage(0);
    load_stage(1);

    const int arow = wm * (MT * 16) + (lane & 7) + ((lane >> 3) & 1) * 8;
    const int akb  = (lane >> 4) * 16;
    const int brow = wn * 32 + (lane >> 4) * 8 + (lane & 7);
    const int bkb  = ((lane >> 3) & 1) * 16;

    for (int c = 0; c < NC; c++) {
        if (c + 1 < NC) asm volatile("cp.async.wait_group 1;" ::: "memory");
        else            asm volatile("cp.async.wait_group 0;" ::: "memory");
        __syncthreads();
        if (c + 2 < NC) load_stage(c + 2);

        const uint32_t stg = smb + (c % 3) * SBF;
        #pragma unroll
        for (int ks = 0; ks < 4; ks++) {
            uint32_t ah[MT][4], bh[4][2];
            #pragma unroll
            for (int mt = 0; mt < MT; mt++) {
                uint32_t so = SWZ128((uint32_t)((arow + mt * 16) * 128 + ks * 32 + akb));
                ldsm4(ah[mt], stg + so);
            }
            #pragma unroll
            for (int jj = 0; jj < 2; jj++) {
                uint32_t so = SWZ128((uint32_t)((brow + jj * 16) * 128 + ks * 32 + bkb));
                uint32_t t[4];
                ldsm4(t, stg + OBH + so);
                bh[jj * 2][0] = t[0]; bh[jj * 2][1] = t[1];
                bh[jj * 2 + 1][0] = t[2]; bh[jj * 2 + 1][1] = t[3];
            }
            #pragma unroll
            for (int mt = 0; mt < MT; mt++)
                #pragma unroll
                for (int nt = 0; nt < 4; nt++)
                    mma16816h(acc[mt][nt], ah[mt], bh[nt]);
        }
    }

    const int rb = m0 + wm * (MT * 16) + (lane >> 2);
    const int cb = n0 + wn * 32 + (lane & 3) * 2;
    #pragma unroll
    for (int mt = 0; mt < MT; mt++) {
        #pragma unroll
        for (int nt = 0; nt < 4; nt++) {
            int r0 = rb + mt * 16;
            int cc = cb + nt * 8;
            float2 b = *(const float2*)(bias + cc);
            float2 v0, v1;
            v0.x = acc[mt][nt][0] + b.x; v0.y = acc[mt][nt][1] + b.y;
            v1.x = acc[mt][nt][2] + b.x; v1.y = acc[mt][nt][3] + b.y;
            *(float2*)(C + (size_t)r0 * N + cc)       = v0;
            *(float2*)(C + (size_t)(r0 + 8) * N + cc) = v1;
        }
    }
}

#define GEMM_SMEM_MT4 (3 * (16384 + 16384))   // 98304
#define GEMM_SMEM_MT2 (3 * (8192 + 16384))    // 73728

// ---------------------------------------------------------------------------
// Fused RoPE (no sign flip) + fp16 pack to head-major [NHEAD][SEQ][80].
// ---------------------------------------------------------------------------
__global__ void rope_pack(const float* __restrict__ qkv,
                          const float* __restrict__ cosT,
                          const float* __restrict__ sinT,
                          __half* __restrict__ Qh, __half* __restrict__ Kh,
                          __half* __restrict__ Vh) {
    int idx = blockIdx.x * blockDim.x + threadIdx.x;
    if (idx >= SEQ * NHEAD * HDIM) return;
    int d  = idx % HDIM;
    int th = idx / HDIM;
    int h  = th & 31;
    int t  = th >> 5;

    const float* base = qkv + (size_t)t * OPSIZE + h * HDIM;
    float q = base[d];
    float k = base[NEMBD + d];
    float v = base[2 * NEMBD + d];
    if (d < RD) {
        float c = cosT[t * RD + d];
        float s = sinT[t * RD + d];
        int dp = (d < 16) ? d + 16 : d - 16;
        q = q * c + base[dp] * s;
        k = k * c + base[NEMBD + dp] * s;
    }
    size_t o = ((size_t)h * SEQ + t) * HDIM + d;
    Qh[o] = __float2half(q * 0.11180339887498948f);
    Kh[o] = __float2half(k);
    Vh[o] = __float2half(v);
}

// ---------------------------------------------------------------------------
// HMMA fp16 flash attention (causal), work-balanced pairs (unchanged R16).
// ---------------------------------------------------------------------------
#define FA_SMEM (16384 + 2 * 32768)   // 81920

__global__ __launch_bounds__(128, 2)
void flash_fp16(const __half* __restrict__ Qh, const __half* __restrict__ Kh,
                const __half* __restrict__ Vh, __half* __restrict__ att) {
    extern __shared__ char sm[];
    const uint32_t smb = smem_u32(sm);
    const int h = blockIdx.y;
    const int pair = blockIdx.x;
    const int tid = threadIdx.x;
    const int lane = tid & 31;
    const int wid = tid >> 5;

    const __half* Kg = Kh + (size_t)h * SEQ * HDIM;
    const __half* Vg = Vh + (size_t)h * SEQ * HDIM;
    const uint32_t SQ = smb;

    const int krow = (lane >> 4) * 8 + (lane & 7);
    const int kcol = ((lane >> 3) & 1) * 8;
    const int vrow = (lane & 7) + ((lane >> 3) & 1) * 8;
    const int vcol = (lane >> 4) * 8;

    auto load_kv = [&](int kb, int s) {
        const __half* kg = Kg + (size_t)kb * 64 * HDIM;
        const __half* vg = Vg + (size_t)kb * 64 * HDIM;
        uint32_t SK = smb + 16384 + s * 32768;
        uint32_t SV = SK + 16384;
        #pragma unroll
        for (int i = 0; i < 5; i++) {
            int id = tid + i * 128;
            int r = id / 10, c = id - r * 10;
            uint32_t o = TOFF(r, c * 8);
            cp_async16(SK + o, kg + r * HDIM + c * 8);
            cp_async16(SV + o, vg + r * HDIM + c * 8);
        }
        asm volatile("cp.async.commit_group;" ::: "memory");
    };

    #pragma unroll 1
    for (int half = 0; half < 2; half++) {
        const int qb = half ? (NQB - 1 - pair) : pair;
        const int q0 = qb * 64;
        const __half* Qg = Qh + ((size_t)h * SEQ + q0) * HDIM;

        #pragma unroll
        for (int i = 0; i < 5; i++) {
            int id = tid + i * 128;
            int r = id / 10, c = id - r * 10;
            cp_async16(SQ + TOFF(r, c * 8), Qg + r * HDIM + c * 8);
        }
        asm volatile("cp.async.commit_group;" ::: "memory");
        load_kv(0, 0);
        asm volatile("cp.async.wait_group 0;" ::: "memory");
        __syncthreads();

        uint32_t qf[5][4];
        {
            int row = wid * 16 + (lane & 7) + ((lane >> 3) & 1) * 8;
            #pragma unroll
            for (int ks = 0; ks < 5; ks++) {
                int col = ks * 16 + (lane >> 4) * 8;
                ldsm4(qf[ks], SQ + TOFF(row, col));
            }
        }

        float m0 = -1e30f, m1 = -1e30f, l0 = 0.f, l1 = 0.f;
        float oa[10][4];
        #pragma unroll
        for (int dt = 0; dt < 10; dt++)
            #pragma unroll
            for (int q = 0; q < 4; q++) oa[dt][q] = 0.f;

        for (int kb = 0; kb <= qb; kb++) {
            const int s = kb & 1;
            if (kb < qb) {
                load_kv(kb + 1, s ^ 1);
                asm volatile("cp.async.wait_group 1;" ::: "memory");
            } else {
                asm volatile("cp.async.wait_group 0;" ::: "memory");
            }
            __syncthreads();
            const uint32_t SK = smb + 16384 + s * 32768;
            const uint32_t SV = SK + 16384;

            float sa[8][4];
            #pragma unroll
            for (int nt = 0; nt < 8; nt++)
                #pragma unroll
                for (int q = 0; q < 4; q++) sa[nt][q] = 0.f;

            #pragma unroll
            for (int ks = 0; ks < 5; ks++) {
                int col = ks * 16 + kcol;
                #pragma unroll
                for (int np = 0; np < 4; np++) {
                    uint32_t t[4];
                    ldsm4(t, SK + TOFF(np * 16 + krow, col));
                    uint32_t b0[2] = { t[0], t[1] };
                    uint32_t b1[2] = { t[2], t[3] };
                    mma16816h(sa[2 * np],     qf[ks], b0);
                    mma16816h(sa[2 * np + 1], qf[ks], b1);
                }
            }

            if (kb == qb) {
                int i0 = wid * 16 + (lane >> 2);
                int i1 = i0 + 8;
                #pragma unroll
                for (int nt = 0; nt < 8; nt++) {
                    int j = nt * 8 + (lane & 3) * 2;
                    if (j     > i0) sa[nt][0] = -1e30f;
                    if (j + 1 > i0) sa[nt][1] = -1e30f;
                    if (j     > i1) sa[nt][2] = -1e30f;
                    if (j + 1 > i1) sa[nt][3] = -1e30f;
                }
            }

            float mx0 = -1e30f, mx1 = -1e30f;
            #pragma unroll
            for (int nt = 0; nt < 8; nt++) {
                mx0 = fmaxf(mx0, fmaxf(sa[nt][0], sa[nt][1]));
                mx1 = fmaxf(mx1, fmaxf(sa[nt][2], sa[nt][3]));
            }
            mx0 = fmaxf(mx0, __shfl_xor_sync(0xffffffffu, mx0, 1));
            mx0 = fmaxf(mx0, __shfl_xor_sync(0xffffffffu, mx0, 2));
            mx1 = fmaxf(mx1, __shfl_xor_sync(0xffffffffu, mx1, 1));
            mx1 = fmaxf(mx1, __shfl_xor_sync(0xffffffffu, mx1, 2));
            float mn0 = fmaxf(m0, mx0), mn1 = fmaxf(m1, mx1);
            float a0 = __expf(m0 - mn0), a1 = __expf(m1 - mn1);
            m0 = mn0; m1 = mn1;

            float lp0 = 0.f, lp1 = 0.f;
            #pragma unroll
            for (int nt = 0; nt < 8; nt++) {
                sa[nt][0] = __expf(sa[nt][0] - mn0);
                sa[nt][1] = __expf(sa[nt][1] - mn0);
                sa[nt][2] = __expf(sa[nt][2] - mn1);
                sa[nt][3] = __expf(sa[nt][3] - mn1);
                lp0 += sa[nt][0] + sa[nt][1];
                lp1 += sa[nt][2] + sa[nt][3];
            }
            lp0 += __shfl_xor_sync(0xffffffffu, lp0, 1);
            lp0 += __shfl_xor_sync(0xffffffffu, lp0, 2);
            lp1 += __shfl_xor_sync(0xffffffffu, lp1, 1);
            lp1 += __shfl_xor_sync(0xffffffffu, lp1, 2);
            l0 = l0 * a0 + lp0;
            l1 = l1 * a1 + lp1;

            #pragma unroll
            for (int dt = 0; dt < 10; dt++) {
                oa[dt][0] *= a0; oa[dt][1] *= a0;
                oa[dt][2] *= a1; oa[dt][3] *= a1;
            }

            uint32_t pf[4][4];
            #pragma unroll
            for (int kt = 0; kt < 4; kt++) {
                pf[kt][0] = h2u(sa[2 * kt][0],     sa[2 * kt][1]);
                pf[kt][1] = h2u(sa[2 * kt][2],     sa[2 * kt][3]);
                pf[kt][2] = h2u(sa[2 * kt + 1][0], sa[2 * kt + 1][1]);
                pf[kt][3] = h2u(sa[2 * kt + 1][2], sa[2 * kt + 1][3]);
            }

            #pragma unroll
            for (int kt = 0; kt < 4; kt++) {
                #pragma unroll
                for (int dp = 0; dp < 5; dp++) {
                    uint32_t t[4];
                    ldsm4t(t, SV + TOFF(kt * 16 + vrow, dp * 16 + vcol));
                    uint32_t b0[2] = { t[0], t[1] };
                    uint32_t b1[2] = { t[2], t[3] };
                    mma16816h(oa[2 * dp],     pf[kt], b0);
                    mma16816h(oa[2 * dp + 1], pf[kt], b1);
                }
            }
            __syncthreads();
        }

        float inv0 = 1.f / l0, inv1 = 1.f / l1;
        int r0 = q0 + wid * 16 + (lane >> 2);
        int dc = (lane & 3) * 2;
        #pragma unroll
        for (int dt = 0; dt < 10; dt++) {
            int d = dt * 8 + dc;
            __half2* p0 = (__half2*)(att + (size_t)r0 * NEMBD + h * HDIM + d);
            __half2* p1 = (__half2*)(att + (size_t)(r0 + 8) * NEMBD + h * HDIM + d);
            *p0 = __floats2half2_rn(oa[dt][0] * inv0, oa[dt][1] * inv0);
            *p1 = __floats2half2_rn(oa[dt][2] * inv1, oa[dt][3] * inv1);
        }
        __syncthreads();
    }
}

// ---------------------------------------------------------------------------
// Launch
// ---------------------------------------------------------------------------
extern "C" void kernel_launch(void* const* d_in, const int* in_sizes, int n_in,
                              void* d_out, int out_size) {
    const float* hidden = (const float*)d_in[0];
    const float* Wqkv_w = (const float*)d_in[1];
    const float* Wqkv_b = (const float*)d_in[2];
    const float* out_w  = (const float*)d_in[3];
    const float* out_b  = (const float*)d_in[4];
    const float* cosT   = (const float*)d_in[5];
    const float* sinT   = (const float*)d_in[6];
    float* out = (float*)d_out;

    float* qkv;
    cudaGetSymbolAddress((void**)&qkv, g_qkv);
    __half *Ha, *Wq, *Ca, *Ow, *Qh, *Kh, *Vh;
    cudaGetSymbolAddress((void**)&Ha, g_Ha);
    cudaGetSymbolAddress((void**)&Wq, g_Wq);
    cudaGetSymbolAddress((void**)&Ca, g_Ca);
    cudaGetSymbolAddress((void**)&Ow, g_Ow);
    cudaGetSymbolAddress((void**)&Qh, g_Qh);
    cudaGetSymbolAddress((void**)&Kh, g_Kh);
    cudaGetSymbolAddress((void**)&Vh, g_Vh);

    cudaFuncSetAttribute(gemm_fp16<4>, cudaFuncAttributeMaxDynamicSharedMemorySize,
                         GEMM_SMEM_MT4);
    cudaFuncSetAttribute(gemm_fp16<2>, cudaFuncAttributeMaxDynamicSharedMemorySize,
                         GEMM_SMEM_MT2);
    cudaFuncSetAttribute(flash_fp16, cudaFuncAttributeMaxDynamicSharedMemorySize,
                         FA_SMEM);

    // Convert inputs to fp16 (RN truncate)
    {
        int n4 = SEQ * NEMBD / 4;
        cvt_trunc<<<(n4 + 255) / 256, 256>>>(hidden, Ha, n4);
        n4 = OPSIZE * NEMBD / 4;
        cvt_trunc<<<(n4 + 255) / 256, 256>>>(Wqkv_w, Wq, n4);
    }

    // 1) QKV = H @ Wqkv^T + b  (BM=128, 3-stage, single product)
    {
        dim3 grid(OPSIZE / 128, SEQ / 128);
        gemm_fp16<4><<<grid, 256, GEMM_SMEM_MT4>>>(Ha, Wq, Wqkv_b, qkv,
                                                   SEQ, OPSIZE, NEMBD);
    }

    // 2) RoPE + fp16 pack (head-major)
    {
        int total = SEQ * NHEAD * HDIM;
        rope_pack<<<(total + 255) / 256, 256>>>(qkv, cosT, sinT, Qh, Kh, Vh);
    }

    // 3) HMMA causal flash attention, work-balanced pairs -> fp16 att
    {
        dim3 grid(NQB / 2, NHEAD);
        flash_fp16<<<grid, 128, FA_SMEM>>>(Qh, Kh, Vh, Ca);
    }

    // 4) out = att @ out_w^T + out_b  (BM=64, 3-stage, single product)
    {
        int n4 = NEMBD * NEMBD / 4;
        cvt_trunc<<<(n4 + 255) / 256, 256>>>(out_w, Ow, n4);
        dim3 grid(NEMBD / 128, SEQ / 64);
        gemm_fp16<2><<<grid, 256, GEMM_SMEM_MT2>>>(Ca, Ow, out_b, out,
                                                   SEQ, NEMBD, NEMBD);
    }
}